// round 3
// baseline (speedup 1.0000x reference)
#include <cuda_runtime.h>
#include <math.h>
#include <stdint.h>

// Problem dims
#define Bb 64
#define Tt 1024
#define Dd 512
#define Hh 512

// Recurrence partition: 16 clusters (4 batch rows each) x 8 CTAs (64 cols each)
#define NGROUP 16
#define NCOLB  8
#define RROWS  4
#define CCOLS  64

// ---- packed f32x2 helpers (FFMA2 is PTX-only; ptxas won't auto-fuse) ----
__device__ __forceinline__ unsigned long long fma2(unsigned long long a,
                                                   unsigned long long b,
                                                   unsigned long long c) {
    unsigned long long d;
    asm("fma.rn.f32x2 %0, %1, %2, %3;" : "=l"(d) : "l"(a), "l"(b), "l"(c));
    return d;
}
__device__ __forceinline__ unsigned long long pack2(float lo, float hi) {
    unsigned long long d;
    asm("mov.b64 %0, {%1, %2};" : "=l"(d) : "f"(lo), "f"(hi));
    return d;
}
__device__ __forceinline__ float2 unpack2(unsigned long long v) {
    float2 r;
    asm("mov.b64 {%0, %1}, %2;" : "=f"(r.x), "=f"(r.y) : "l"(v));
    return r;
}

// ---- DSMEM helpers ----
__device__ __forceinline__ uint32_t smem_u32(const void* p) {
    uint32_t a;
    asm("{ .reg .u64 t; cvta.to.shared.u64 t, %1; cvt.u32.u64 %0, t; }"
        : "=r"(a) : "l"(p));
    return a;
}
__device__ __forceinline__ uint32_t mapa_u32(uint32_t addr, uint32_t rank) {
    uint32_t r;
    asm("mapa.shared::cluster.u32 %0, %1, %2;" : "=r"(r) : "r"(addr), "r"(rank));
    return r;
}
__device__ __forceinline__ void st_cluster_v4(uint32_t addr, float4 v) {
    asm volatile("st.shared::cluster.v4.f32 [%0], {%1, %2, %3, %4};"
                 :: "r"(addr), "f"(v.x), "f"(v.y), "f"(v.z), "f"(v.w)
                 : "memory");
}
__device__ __forceinline__ void cluster_sync_hw() {
    asm volatile("barrier.cluster.arrive.aligned;" ::: "memory");
    asm volatile("barrier.cluster.wait.aligned;" ::: "memory");
}

// ---------------------------------------------------------------------------
// Phase 1: xw = x @ Wx + b  (M=65536, N=512, K=512) staged into out.
// BM=128, BN=128, BK=16, 256 threads, 8x8 microtile, FFMA2 inner product.
// A LDS are 2-way warp-broadcast; FFMA2 issue rate is the binding floor.
// ---------------------------------------------------------------------------
#define BM 128
#define BN 128
#define BK 16

__global__ __launch_bounds__(256) void xw_gemm_kernel(
    const float* __restrict__ x,
    const float* __restrict__ W,     // (D+H, H); rows [0,D) = Wx
    const float* __restrict__ bias,
    float* __restrict__ out)         // (B*T, H)
{
    __shared__ float As[BK][BM];   // [k][m]
    __shared__ float Bs[BK][BN];   // [k][n]
    const int tid = threadIdx.x;
    const int tx = tid & 15;       // n: 8 cols at tx*8
    const int ty = tid >> 4;       // m: 8 rows at ty*8
    const int m0 = blockIdx.y * BM;
    const int n0 = blockIdx.x * BN;

    unsigned long long acc2[4][8];   // [m-pair][n]
    #pragma unroll
    for (int i = 0; i < 4; i++)
        #pragma unroll
        for (int jj = 0; jj < 8; jj++) acc2[i][jj] = 0ull;

    for (int k0 = 0; k0 < Dd; k0 += BK) {
        // A tile 128x16 -> As[k][m]
        #pragma unroll
        for (int it = 0; it < 2; it++) {
            int idx = tid + it * 256;          // 0..511
            int m   = idx >> 2;                // 0..127
            int kq  = (idx & 3) * 4;
            float4 v = *reinterpret_cast<const float4*>(
                &x[(size_t)(m0 + m) * Dd + k0 + kq]);
            As[kq + 0][m] = v.x; As[kq + 1][m] = v.y;
            As[kq + 2][m] = v.z; As[kq + 3][m] = v.w;
        }
        // B tile 16x128
        #pragma unroll
        for (int it = 0; it < 2; it++) {
            int idx = tid + it * 256;
            int rr  = idx >> 5;                // 0..15
            int c4  = (idx & 31) * 4;          // 0..124
            float4 v = *reinterpret_cast<const float4*>(
                &W[(size_t)(k0 + rr) * Hh + n0 + c4]);
            *reinterpret_cast<float4*>(&Bs[rr][c4]) = v;
        }
        __syncthreads();

        #pragma unroll
        for (int kk = 0; kk < BK; kk++) {
            ulonglong2 a01 = *reinterpret_cast<const ulonglong2*>(&As[kk][ty * 8]);
            ulonglong2 a23 = *reinterpret_cast<const ulonglong2*>(&As[kk][ty * 8 + 4]);
            unsigned long long av[4] = {a01.x, a01.y, a23.x, a23.y};
            float4 b0 = *reinterpret_cast<const float4*>(&Bs[kk][tx * 8]);
            float4 b1 = *reinterpret_cast<const float4*>(&Bs[kk][tx * 8 + 4]);
            unsigned long long bv[8] = {
                pack2(b0.x, b0.x), pack2(b0.y, b0.y),
                pack2(b0.z, b0.z), pack2(b0.w, b0.w),
                pack2(b1.x, b1.x), pack2(b1.y, b1.y),
                pack2(b1.z, b1.z), pack2(b1.w, b1.w)};
            #pragma unroll
            for (int i = 0; i < 4; i++)
                #pragma unroll
                for (int jj = 0; jj < 8; jj++)
                    acc2[i][jj] = fma2(av[i], bv[jj], acc2[i][jj]);
        }
        __syncthreads();
    }

    float4 bb0 = *reinterpret_cast<const float4*>(&bias[n0 + tx * 8]);
    float4 bb1 = *reinterpret_cast<const float4*>(&bias[n0 + tx * 8 + 4]);
    #pragma unroll
    for (int i = 0; i < 4; i++) {
        float2 u[8];
        #pragma unroll
        for (int jj = 0; jj < 8; jj++) u[jj] = unpack2(acc2[i][jj]);
        int m = m0 + ty * 8 + 2 * i;
        float4 lo0 = make_float4(u[0].x + bb0.x, u[1].x + bb0.y,
                                 u[2].x + bb0.z, u[3].x + bb0.w);
        float4 lo1 = make_float4(u[4].x + bb1.x, u[5].x + bb1.y,
                                 u[6].x + bb1.z, u[7].x + bb1.w);
        float4 hi0 = make_float4(u[0].y + bb0.x, u[1].y + bb0.y,
                                 u[2].y + bb0.z, u[3].y + bb0.w);
        float4 hi1 = make_float4(u[4].y + bb1.x, u[5].y + bb1.y,
                                 u[6].y + bb1.z, u[7].y + bb1.w);
        float* row0 = &out[(size_t)m * Hh + n0 + tx * 8];
        float* row1 = &out[(size_t)(m + 1) * Hh + n0 + tx * 8];
        *reinterpret_cast<float4*>(row0)     = lo0;
        *reinterpret_cast<float4*>(row0 + 4) = lo1;
        *reinterpret_cast<float4*>(row1)     = hi0;
        *reinterpret_cast<float4*>(row1 + 4) = hi1;
    }
}

// ---------------------------------------------------------------------------
// Phase 2: persistent recurrence, 8-CTA clusters, Wh in registers, h exchange
// via DSMEM double buffer + one cluster.sync per step.
// 256 threads = (64 cols x 4 k-chunks); each thread holds 128 Wh values
// (64 packed f32x2 regs) for its (column, k-chunk).
// ---------------------------------------------------------------------------
__global__ __launch_bounds__(256, 1) __cluster_dims__(NCOLB, 1, 1)
void recur_kernel(
    const float* __restrict__ W,   // rows [D, D+H) = Wh
    float* __restrict__ out)       // (B, T, H); holds xw, becomes h
{
    __shared__ float hs[2][RROWS][Hh];          // 16 KB double-buffered h
    __shared__ float red[4][RROWS][CCOLS];      // 4 KB k-chunk partials
    __shared__ float fin[RROWS][CCOLS];         // 1 KB final h slice

    const int tid  = threadIdx.x;
    const int j    = blockIdx.x;                // cluster rank / col block
    const int g    = blockIdx.y;                // batch group
    const int col0 = j * CCOLS;
    const int c    = tid & 63;                  // column within block
    const int q    = tid >> 6;                  // k-chunk (warp-uniform)
    const int r2   = tid >> 6;                  // epilogue row
    const int ce   = tid & 63;                  // epilogue col
    const int row  = g * RROWS + r2;            // batch index

    const uint32_t hs_base  = smem_u32(&hs[0][0][0]);
    const uint32_t fin_base = smem_u32(&fin[0][0]);

    // Load Wh slice into registers
    unsigned long long w2[64];
    #pragma unroll
    for (int i = 0; i < 64; i++) {
        int k = q * 128 + 2 * i;
        float a = W[(size_t)(Dd + k) * Hh + col0 + c];
        float b = W[(size_t)(Dd + k + 1) * Hh + col0 + c];
        w2[i] = pack2(a, b);
    }

    // t = 0: h_0 = 0 -> h = tanh(xw_0); broadcast into buffer 0
    {
        size_t o = ((size_t)row * Tt) * Hh + col0 + ce;
        float v = tanhf(__ldcg(&out[o]));
        out[o] = v;
        fin[r2][ce] = v;
        __syncthreads();
        #pragma unroll
        for (int it = 0; it < 2; it++) {
            int s = tid + it * 256;             // 0..511
            uint32_t rank  = s >> 6;            // 0..7
            int      chunk = s & 63;            // float4 index in fin
            float4 v4 = reinterpret_cast<const float4*>(fin_base == 0 ? 0 : &fin[0][0])[chunk];
            // dst: peer hs[0][r][col0 + ...]
            int rr = chunk >> 4, c16 = chunk & 15;
            uint32_t off = hs_base + (uint32_t)(rr * (Hh * 4) + col0 * 4 + c16 * 16);
            st_cluster_v4(mapa_u32(off, rank), v4);
        }
        cluster_sync_hw();
    }

    for (int t = 1; t < Tt; t++) {
        // Prefetch xw_t (independent of compute; hides L2/DRAM latency)
        float xw_v = __ldcg(&out[((size_t)row * Tt + t) * Hh + col0 + ce]);

        const int bp = (t - 1) & 1;             // read buffer
        const int bc = t & 1;                   // write buffer

        // Partial dots: rows 0..3, column c, k-chunk q; hs reads warp-broadcast
        unsigned long long acc[RROWS] = {0ull, 0ull, 0ull, 0ull};
        const ulonglong2* hp0 = reinterpret_cast<const ulonglong2*>(&hs[bp][0][q * 128]);
        const ulonglong2* hp1 = reinterpret_cast<const ulonglong2*>(&hs[bp][1][q * 128]);
        const ulonglong2* hp2 = reinterpret_cast<const ulonglong2*>(&hs[bp][2][q * 128]);
        const ulonglong2* hp3 = reinterpret_cast<const ulonglong2*>(&hs[bp][3][q * 128]);
        #pragma unroll
        for (int i = 0; i < 32; i++) {
            ulonglong2 h0 = hp0[i], h1 = hp1[i], h2 = hp2[i], h3 = hp3[i];
            acc[0] = fma2(w2[2 * i], h0.x, acc[0]);
            acc[1] = fma2(w2[2 * i], h1.x, acc[1]);
            acc[2] = fma2(w2[2 * i], h2.x, acc[2]);
            acc[3] = fma2(w2[2 * i], h3.x, acc[3]);
            acc[0] = fma2(w2[2 * i + 1], h0.y, acc[0]);
            acc[1] = fma2(w2[2 * i + 1], h1.y, acc[1]);
            acc[2] = fma2(w2[2 * i + 1], h2.y, acc[2]);
            acc[3] = fma2(w2[2 * i + 1], h3.y, acc[3]);
        }
        #pragma unroll
        for (int rr = 0; rr < RROWS; rr++) {
            float2 u = unpack2(acc[rr]);
            red[q][rr][c] = u.x + u.y;
        }
        __syncthreads();

        // Reduce k-chunks, add xw, tanh, emit
        float s = red[0][r2][ce] + red[1][r2][ce] + red[2][r2][ce] + red[3][r2][ce];
        float v = tanhf(s + xw_v);
        out[((size_t)row * Tt + t) * Hh + col0 + ce] = v;
        fin[r2][ce] = v;

        if (t < Tt - 1) {
            __syncthreads();
            // Broadcast slice into every cluster CTA's hs[bc]
            #pragma unroll
            for (int it = 0; it < 2; it++) {
                int s2 = tid + it * 256;
                uint32_t rank  = s2 >> 6;
                int      chunk = s2 & 63;
                float4 v4 = reinterpret_cast<const float4*>(&fin[0][0])[chunk];
                int rr = chunk >> 4, c16 = chunk & 15;
                uint32_t off = hs_base + (uint32_t)(bc * (RROWS * Hh * 4) +
                               rr * (Hh * 4) + col0 * 4 + c16 * 16);
                st_cluster_v4(mapa_u32(off, rank), v4);
            }
            cluster_sync_hw();
        }
    }
}

// ---------------------------------------------------------------------------
extern "C" void kernel_launch(void* const* d_in, const int* in_sizes, int n_in,
                              void* d_out, int out_size)
{
    const float* x    = (const float*)d_in[0];
    const float* W    = (const float*)d_in[1];
    const float* bias = (const float*)d_in[2];
    float* out        = (float*)d_out;

    // Phase 1: stage xw into out
    dim3 gg(Hh / BN, (Bb * Tt) / BM);
    xw_gemm_kernel<<<gg, 256>>>(x, W, bias, out);

    // Phase 2: clustered persistent recurrence (16 clusters x 8 CTAs)
    recur_kernel<<<dim3(NCOLB, NGROUP), 256>>>(W, out);
}